// round 2
// baseline (speedup 1.0000x reference)
#include <cuda_runtime.h>
#include <cuda_bf16.h>
#include <cfloat>
#include <math.h>

#define NN 200000
#define EE 3200000
#define BB 2000
#define NPG 100
#define HH 32
#define KK 60
#define DD 97
#define TG 12   // graphs per block in tail2

// ---------------- device scratch ----------------
__device__ float g_deg[NN];
__device__ float g_dis[NN];
__device__ int   g_cnt[NN];
__device__ int   g_off[NN];
__device__ int   g_cur[NN];
__device__ int   g_csr_src[EE];
__device__ float g_csr_norm[EE];
__device__ float g_h [NN * 32];   // x0@W0, then reused as scalar buffer for layer 3
__device__ float g_h1[NN * 32];
__device__ float g_h2[NN * 32];
__device__ float g_h3[NN * 32];
__device__ float g_h4[NN];
__device__ float g_flat[BB * 832];
__device__ int   g_bsum[256];

// ---------------- CSR build ----------------
__global__ void k_init() {
    int i = blockIdx.x * blockDim.x + threadIdx.x;
    if (i < NN) { g_deg[i] = 1.0f; g_cnt[i] = 0; }  // self loop weight 1
}

__global__ void k_hist(const int* __restrict__ ei, const float* __restrict__ ew) {
    int e = blockIdx.x * blockDim.x + threadIdx.x;
    if (e < EE) {
        int dst = ei[EE + e];
        atomicAdd(&g_deg[dst], ew[e]);   // void use -> REDG
        atomicAdd(&g_cnt[dst], 1);
    }
}

// exclusive scan over cnt (also computes dis = rsqrt(deg))
__global__ void k_scan1() {
    __shared__ int sh[1024];
    int tid = threadIdx.x;
    int i = blockIdx.x * 1024 + tid;
    int v = 0;
    if (i < NN) {
        v = g_cnt[i];
        g_dis[i] = rsqrtf(g_deg[i]);
    }
    sh[tid] = v;
    __syncthreads();
    for (int ofs = 1; ofs < 1024; ofs <<= 1) {
        int t = (tid >= ofs) ? sh[tid - ofs] : 0;
        __syncthreads();
        sh[tid] += t;
        __syncthreads();
    }
    int incl = sh[tid];
    if (i < NN) g_off[i] = incl - v;
    if (tid == 1023) g_bsum[blockIdx.x] = incl;
}

__global__ void k_scan2(int nb) {
    __shared__ int sh[256];
    int tid = threadIdx.x;
    int v = (tid < nb) ? g_bsum[tid] : 0;
    sh[tid] = v;
    __syncthreads();
    for (int ofs = 1; ofs < 256; ofs <<= 1) {
        int t = (tid >= ofs) ? sh[tid - ofs] : 0;
        __syncthreads();
        sh[tid] += t;
        __syncthreads();
    }
    if (tid < nb) g_bsum[tid] = sh[tid] - v;
}

__global__ void k_scan3() {
    int tid = threadIdx.x;
    int i = blockIdx.x * 1024 + tid;
    if (i < NN) {
        int o = g_off[i] + g_bsum[blockIdx.x];
        g_off[i] = o;
        g_cur[i] = o;
    }
}

__global__ void k_fill(const int* __restrict__ ei, const float* __restrict__ ew) {
    int e = blockIdx.x * blockDim.x + threadIdx.x;
    if (e < EE) {
        int src = ei[e];
        int dst = ei[EE + e];
        int pos = atomicAdd(&g_cur[dst], 1);
        g_csr_src[pos]  = src;
        g_csr_norm[pos] = g_dis[src] * ew[e] * g_dis[dst];
    }
}

// ---------------- GCN layers ----------------
// layer 0 matmul: fused embedding gather + [N,96]@[96,32] -> g_h
__global__ void k_mm0(const int* __restrict__ w, const int* __restrict__ z1,
                      const int* __restrict__ z2,
                      const float* __restrict__ emb_w, const float* __restrict__ emb_z1,
                      const float* __restrict__ emb_z2, const float* __restrict__ W0) {
    __shared__ float Ws[96 * 32];
    for (int i = threadIdx.x; i < 96 * 32; i += blockDim.x) Ws[i] = W0[i];
    __syncthreads();
    int lane = threadIdx.x & 31;
    int warp = (blockIdx.x * blockDim.x + threadIdx.x) >> 5;
    int nwarps = (gridDim.x * blockDim.x) >> 5;
    for (int n = warp; n < NN; n += nwarps) {
        float r0 = emb_w [w [n] * 32 + lane];
        float r1 = emb_z1[z1[n] * 32 + lane];
        float r2 = emb_z2[z2[n] * 32 + lane];
        float acc = 0.f;
#pragma unroll
        for (int k = 0; k < 32; k++) acc += __shfl_sync(0xffffffffu, r0, k) * Ws[k * 32 + lane];
#pragma unroll
        for (int k = 0; k < 32; k++) acc += __shfl_sync(0xffffffffu, r1, k) * Ws[(32 + k) * 32 + lane];
#pragma unroll
        for (int k = 0; k < 32; k++) acc += __shfl_sync(0xffffffffu, r2, k) * Ws[(64 + k) * 32 + lane];
        g_h[n * 32 + lane] = acc;
    }
}

// aggregate 32ch from x over CSR + bias + tanh (layer 0 tail: x is already x@W)
__global__ void k_agg32(const float* __restrict__ x, const float* __restrict__ bias,
                        float* __restrict__ out) {
    int lane = threadIdx.x & 31;
    int warp = (blockIdx.x * blockDim.x + threadIdx.x) >> 5;
    int nwarps = (gridDim.x * blockDim.x) >> 5;
    float bl = bias[lane];
    for (int n = warp; n < NN; n += nwarps) {
        float dn = g_dis[n];
        float accA = dn * dn * x[n * 32 + lane];
        float accB = 0.f;
        int i = g_off[n], e0 = i + g_cnt[n];
        for (; i + 2 <= e0; i += 2) {
            int   sA = g_csr_src[i],     sB = g_csr_src[i + 1];
            float nA = g_csr_norm[i],    nB = g_csr_norm[i + 1];
            accA += nA * x[sA * 32 + lane];
            accB += nB * x[sB * 32 + lane];
        }
        if (i < e0) accA += g_csr_norm[i] * x[g_csr_src[i] * 32 + lane];
        out[n * 32 + lane] = tanhf(accA + accB + bl);
    }
}

// fused: a = agg(x) over CSR (32ch), then y = a@W + b, tanh  (layers 1,2)
__global__ void k_aggmm(const float* __restrict__ x, const float* __restrict__ W,
                        const float* __restrict__ bias, float* __restrict__ out) {
    int lane = threadIdx.x & 31;
    int warp = (blockIdx.x * blockDim.x + threadIdx.x) >> 5;
    int nwarps = (gridDim.x * blockDim.x) >> 5;
    float wr[32];
#pragma unroll
    for (int k = 0; k < 32; k++) wr[k] = W[k * 32 + lane];
    float bl = bias[lane];
    for (int n = warp; n < NN; n += nwarps) {
        float dn = g_dis[n];
        float accA = dn * dn * x[n * 32 + lane];
        float accB = 0.f;
        int i = g_off[n], e0 = i + g_cnt[n];
        for (; i + 2 <= e0; i += 2) {
            int   sA = g_csr_src[i],     sB = g_csr_src[i + 1];
            float nA = g_csr_norm[i],    nB = g_csr_norm[i + 1];
            accA += nA * x[sA * 32 + lane];
            accB += nB * x[sB * 32 + lane];
        }
        if (i < e0) accA += g_csr_norm[i] * x[g_csr_src[i] * 32 + lane];
        float a = accA + accB;
        float y = bl;
#pragma unroll
        for (int k = 0; k < 32; k++) y += __shfl_sync(0xffffffffu, a, k) * wr[k];
        out[n * 32 + lane] = tanhf(y);
    }
}

// [N,32]@[32,1] -> g_h[n]  (layer 3 pre-multiply: cheaper to aggregate scalars)
__global__ void k_mm1(const float* __restrict__ x, const float* __restrict__ W3) {
    int lane = threadIdx.x & 31;
    int warp = (blockIdx.x * blockDim.x + threadIdx.x) >> 5;
    int nwarps = (gridDim.x * blockDim.x) >> 5;
    float w3 = W3[lane];
    for (int n = warp; n < NN; n += nwarps) {
        float v = x[n * 32 + lane] * w3;
#pragma unroll
        for (int o = 16; o > 0; o >>= 1) v += __shfl_down_sync(0xffffffffu, v, o);
        if (lane == 0) g_h[n] = v;
    }
}

// aggregate scalar (layer 3)
__global__ void k_agg1(const float* __restrict__ b3) {
    int lane = threadIdx.x & 31;
    int warp = (blockIdx.x * blockDim.x + threadIdx.x) >> 5;
    int nwarps = (gridDim.x * blockDim.x) >> 5;
    float b = b3[0];
    for (int n = warp; n < NN; n += nwarps) {
        int s0 = g_off[n], e0 = s0 + g_cnt[n];
        float acc = 0.f;
        for (int i = s0 + lane; i < e0; i += 32)
            acc += g_csr_norm[i] * g_h[g_csr_src[i]];
#pragma unroll
        for (int o = 16; o > 0; o >>= 1) acc += __shfl_down_sync(0xffffffffu, acc, o);
        if (lane == 0) {
            float dn = g_dis[n];
            g_h4[n] = tanhf(acc + dn * dn * g_h[n] + b);
        }
    }
}

// ---------------- tail1: sort-pool + conv1 + maxpool + conv2 -> g_flat ----------------
__global__ void k_tail1(const float* __restrict__ c1W, const float* __restrict__ c1b,
                        const float* __restrict__ c2W, const float* __restrict__ c2b) {
    __shared__ float s_vals[128];
    __shared__ int   s_idx[128];
    __shared__ float s_xs[KK * DD];     // 23280B
    __shared__ float s_w[2560];         // c1W then c2W
    __shared__ float s_t1[16 * KK];
    __shared__ float s_pool[16 * 30];

    int b = blockIdx.x;
    int t = threadIdx.x;
    int g0 = b * NPG;

    // sort keys desc (index asc tiebreak = jnp.argsort stability)
    float v = (t < NPG) ? g_h4[g0 + t] : -FLT_MAX;
    int   id = (t < NPG) ? t : 0x7fffffff;
    s_vals[t] = v; s_idx[t] = id;
    __syncthreads();
    for (int k = 2; k <= 128; k <<= 1) {
        for (int j = k >> 1; j > 0; j >>= 1) {
            int ixj = t ^ j;
            if (ixj > t) {
                float va = s_vals[t],  vb = s_vals[ixj];
                int   ia = s_idx[t],   ib = s_idx[ixj];
                bool before = (va > vb) || (va == vb && ia < ib);
                bool up = ((t & k) == 0);
                if (up ? !before : before) {
                    s_vals[t] = vb; s_vals[ixj] = va;
                    s_idx[t]  = ib; s_idx[ixj]  = ia;
                }
            }
            __syncthreads();
        }
    }

    // gather top-K features [K][D]
    for (int q = t; q < KK * DD; q += 128) {
        int kk = q / DD, dd = q - kk * DD;
        int node = g0 + s_idx[kk];
        float val;
        if      (dd < 32) val = g_h1[node * 32 + dd];
        else if (dd < 64) val = g_h2[node * 32 + dd - 32];
        else if (dd < 96) val = g_h3[node * 32 + dd - 64];
        else              val = g_h4[node];
        s_xs[q] = val;
    }
    for (int q = t; q < 16 * DD; q += 128) s_w[q] = c1W[q];
    __syncthreads();

    // conv1 (per-slot projection) + relu
    for (int q = t; q < 16 * KK; q += 128) {
        int o = q / KK, kk = q - o * KK;
        float acc = c1b[o];
        for (int dd = 0; dd < DD; dd++) acc += s_xs[kk * DD + dd] * s_w[o * DD + dd];
        s_t1[o * KK + kk] = fmaxf(acc, 0.f);
    }
    __syncthreads();

    // maxpool(2,2) + stage c2W
    for (int q = t; q < 16 * 30; q += 128) {
        int o = q / 30, p = q - o * 30;
        s_pool[o * 30 + p] = fmaxf(s_t1[o * KK + 2 * p], s_t1[o * KK + 2 * p + 1]);
    }
    for (int q = t; q < 2560; q += 128) s_w[q] = c2W[q];
    __syncthreads();

    // conv2 + relu -> g_flat
    for (int q = t; q < 832; q += 128) {
        int o = q / 26, p = q - o * 26;
        float acc = c2b[o];
        for (int i = 0; i < 16; i++) {
#pragma unroll
            for (int tt = 0; tt < 5; tt++)
                acc += s_pool[i * 30 + p + tt] * s_w[o * 80 + i * 5 + tt];
        }
        g_flat[b * 832 + o * 26 + p] = fmaxf(acc, 0.f);
    }
}

// ---------------- tail2: [B,832]@[832,128] -> relu -> @[128,1] ----------------
__global__ void k_tail2(const float* __restrict__ l1W, const float* __restrict__ l1b,
                        const float* __restrict__ l2W, const float* __restrict__ l2b,
                        float* __restrict__ out) {
    __shared__ float s_flat[TG * 832];   // 39936B
    __shared__ float s_red[TG][4];
    int t = threadIdx.x;
    int b0 = blockIdx.x * TG;
    int ng = min(TG, BB - b0);

    for (int q = t; q < ng * 832; q += 128) s_flat[q] = g_flat[b0 * 832 + q];
    __syncthreads();

    float acc[TG];
#pragma unroll
    for (int g = 0; g < TG; g++) acc[g] = 0.f;

    for (int f = 0; f < 832; f++) {
        float wv = l1W[f * 128 + t];
#pragma unroll
        for (int g = 0; g < TG; g++) acc[g] += s_flat[g * 832 + f] * wv;
    }

    float b1v = l1b[t], w2 = l2W[t];
#pragma unroll
    for (int g = 0; g < TG; g++) {
        float p = fmaxf(acc[g] + b1v, 0.f) * w2;
#pragma unroll
        for (int o = 16; o > 0; o >>= 1) p += __shfl_down_sync(0xffffffffu, p, o);
        if ((t & 31) == 0) s_red[g][t >> 5] = p;
    }
    __syncthreads();
    if (t < ng) out[b0 + t] = s_red[t][0] + s_red[t][1] + s_red[t][2] + s_red[t][3] + l2b[0];
}

// ---------------- launch ----------------
extern "C" void kernel_launch(void* const* d_in, const int* in_sizes, int n_in,
                              void* d_out, int out_size) {
    const int*   z1    = (const int*)  d_in[0];
    const int*   z2    = (const int*)  d_in[1];
    const int*   w     = (const int*)  d_in[2];
    const int*   ei    = (const int*)  d_in[3];
    const float* ew    = (const float*)d_in[5];
    const float* emb_w = (const float*)d_in[6];
    const float* emb_z1= (const float*)d_in[7];
    const float* emb_z2= (const float*)d_in[8];
    const float* W0 = (const float*)d_in[9];
    const float* b0 = (const float*)d_in[10];
    const float* W1 = (const float*)d_in[11];
    const float* b1 = (const float*)d_in[12];
    const float* W2 = (const float*)d_in[13];
    const float* b2 = (const float*)d_in[14];
    const float* W3 = (const float*)d_in[15];
    const float* b3 = (const float*)d_in[16];
    const float* c1W = (const float*)d_in[17];
    const float* c1b = (const float*)d_in[18];
    const float* c2W = (const float*)d_in[19];
    const float* c2b = (const float*)d_in[20];
    const float* l1W = (const float*)d_in[21];
    const float* l1b = (const float*)d_in[22];
    const float* l2W = (const float*)d_in[23];
    const float* l2b = (const float*)d_in[24];
    float* out = (float*)d_out;

    const int nb_n = (NN + 255) / 256;
    const int nb_e = (EE + 255) / 256;
    const int nb_scan = (NN + 1023) / 1024;   // 196
    const int GRID = 1480;

    float *hh, *h1, *h2, *h3;
    cudaGetSymbolAddress((void**)&hh, g_h);
    cudaGetSymbolAddress((void**)&h1, g_h1);
    cudaGetSymbolAddress((void**)&h2, g_h2);
    cudaGetSymbolAddress((void**)&h3, g_h3);

    // CSR build
    k_init<<<nb_n, 256>>>();
    k_hist<<<nb_e, 256>>>(ei, ew);
    k_scan1<<<nb_scan, 1024>>>();
    k_scan2<<<1, 256>>>(nb_scan);
    k_scan3<<<nb_scan, 1024>>>();
    k_fill<<<nb_e, 256>>>(ei, ew);

    // GCN stack
    k_mm0  <<<GRID, 256>>>(w, z1, z2, emb_w, emb_z1, emb_z2, W0);
    k_agg32<<<GRID, 256>>>(hh, b0, h1);
    k_aggmm<<<GRID, 256>>>(h1, W1, b1, h2);
    k_aggmm<<<GRID, 256>>>(h2, W2, b2, h3);
    k_mm1  <<<GRID, 256>>>(h3, W3);
    k_agg1 <<<GRID, 256>>>(b3);

    // tail
    k_tail1<<<BB, 128>>>(c1W, c1b, c2W, c2b);
    k_tail2<<<(BB + TG - 1) / TG, 128>>>(l1W, l1b, l2W, l2b, out);
}

// round 3
// speedup vs baseline: 1.0106x; 1.0106x over previous
#include <cuda_runtime.h>
#include <cuda_bf16.h>
#include <cfloat>
#include <math.h>

#define NN 200000
#define EE 3200000
#define BB 2000
#define NPG 100
#define HH 32
#define KK 60
#define DD 97
#define TG 12   // graphs per block in tail2

// ---------------- device scratch ----------------
__device__ float g_deg[NN];
__device__ float g_dis[NN];
__device__ int   g_cnt[NN];
__device__ int   g_off[NN];
__device__ int   g_cur[NN];
__device__ int2  g_csr[EE];       // .x = src, .y = norm (float bits)
__device__ float g_h [NN * 32];   // x@W scratch; also scalar buffer layer 3
__device__ float g_h1[NN * 32];
__device__ float g_h2[NN * 32];
__device__ float g_h3[NN * 32];
__device__ float g_h4[NN];
__device__ float g_flat[BB * 832];
__device__ int   g_bsum[256];

// ---------------- CSR build ----------------
__global__ void k_init() {
    int i = blockIdx.x * blockDim.x + threadIdx.x;
    if (i < NN) { g_deg[i] = 1.0f; g_cnt[i] = 0; }  // self loop weight 1
}

__global__ void k_hist(const int* __restrict__ ei, const float* __restrict__ ew) {
    int e = blockIdx.x * blockDim.x + threadIdx.x;
    if (e < EE) {
        int dst = ei[EE + e];
        atomicAdd(&g_deg[dst], ew[e]);
        atomicAdd(&g_cnt[dst], 1);
    }
}

// exclusive scan over cnt (also computes dis = rsqrt(deg))
__global__ void k_scan1() {
    __shared__ int sh[1024];
    int tid = threadIdx.x;
    int i = blockIdx.x * 1024 + tid;
    int v = 0;
    if (i < NN) {
        v = g_cnt[i];
        g_dis[i] = rsqrtf(g_deg[i]);
    }
    sh[tid] = v;
    __syncthreads();
    for (int ofs = 1; ofs < 1024; ofs <<= 1) {
        int t = (tid >= ofs) ? sh[tid - ofs] : 0;
        __syncthreads();
        sh[tid] += t;
        __syncthreads();
    }
    int incl = sh[tid];
    if (i < NN) g_off[i] = incl - v;
    if (tid == 1023) g_bsum[blockIdx.x] = incl;
}

__global__ void k_scan2(int nb) {
    __shared__ int sh[256];
    int tid = threadIdx.x;
    int v = (tid < nb) ? g_bsum[tid] : 0;
    sh[tid] = v;
    __syncthreads();
    for (int ofs = 1; ofs < 256; ofs <<= 1) {
        int t = (tid >= ofs) ? sh[tid - ofs] : 0;
        __syncthreads();
        sh[tid] += t;
        __syncthreads();
    }
    if (tid < nb) g_bsum[tid] = sh[tid] - v;
}

__global__ void k_scan3() {
    int tid = threadIdx.x;
    int i = blockIdx.x * 1024 + tid;
    if (i < NN) {
        int o = g_off[i] + g_bsum[blockIdx.x];
        g_off[i] = o;
        g_cur[i] = o;
    }
}

__global__ void k_fill(const int* __restrict__ ei, const float* __restrict__ ew) {
    int e = blockIdx.x * blockDim.x + threadIdx.x;
    if (e < EE) {
        int src = ei[e];
        int dst = ei[EE + e];
        int pos = atomicAdd(&g_cur[dst], 1);
        float nrm = g_dis[src] * ew[e] * g_dis[dst];
        g_csr[pos] = make_int2(src, __float_as_int(nrm));
    }
}

// ---------------- GCN layers ----------------
// layer 0 matmul: fused embedding gather + [N,96]@[96,32] -> g_h
__global__ void k_mm0(const int* __restrict__ w, const int* __restrict__ z1,
                      const int* __restrict__ z2,
                      const float* __restrict__ emb_w, const float* __restrict__ emb_z1,
                      const float* __restrict__ emb_z2, const float* __restrict__ W0) {
    __shared__ float Ws[96 * 32];
    for (int i = threadIdx.x; i < 96 * 32; i += blockDim.x) Ws[i] = W0[i];
    __syncthreads();
    int lane = threadIdx.x & 31;
    int warp = (blockIdx.x * blockDim.x + threadIdx.x) >> 5;
    int nwarps = (gridDim.x * blockDim.x) >> 5;
    for (int n = warp; n < NN; n += nwarps) {
        float r0 = emb_w [w [n] * 32 + lane];
        float r1 = emb_z1[z1[n] * 32 + lane];
        float r2 = emb_z2[z2[n] * 32 + lane];
        float acc = 0.f;
#pragma unroll
        for (int k = 0; k < 32; k++) acc += __shfl_sync(0xffffffffu, r0, k) * Ws[k * 32 + lane];
#pragma unroll
        for (int k = 0; k < 32; k++) acc += __shfl_sync(0xffffffffu, r1, k) * Ws[(32 + k) * 32 + lane];
#pragma unroll
        for (int k = 0; k < 32; k++) acc += __shfl_sync(0xffffffffu, r2, k) * Ws[(64 + k) * 32 + lane];
        g_h[n * 32 + lane] = acc;
    }
}

// [N,32]@[32,32] -> g_h (streaming, register-light)
__global__ void k_mm32(const float* __restrict__ x, const float* __restrict__ W) {
    __shared__ float Ws[32 * 32];
    for (int i = threadIdx.x; i < 32 * 32; i += blockDim.x) Ws[i] = W[i];
    __syncthreads();
    int lane = threadIdx.x & 31;
    int warp = (blockIdx.x * blockDim.x + threadIdx.x) >> 5;
    int nwarps = (gridDim.x * blockDim.x) >> 5;
    for (int n = warp; n < NN; n += nwarps) {
        float r = x[n * 32 + lane];
        float acc = 0.f;
#pragma unroll
        for (int k = 0; k < 32; k++) acc += __shfl_sync(0xffffffffu, r, k) * Ws[k * 32 + lane];
        g_h[n * 32 + lane] = acc;
    }
}

// aggregate 32ch from g_h over CSR + bias + tanh; 4 independent chains for MLP
__global__ void k_agg32(const float* __restrict__ bias, float* __restrict__ out) {
    int lane = threadIdx.x & 31;
    int warp = (blockIdx.x * blockDim.x + threadIdx.x) >> 5;
    int nwarps = (gridDim.x * blockDim.x) >> 5;
    float bl = bias[lane];
    for (int n = warp; n < NN; n += nwarps) {
        float dn = g_dis[n];
        float a0 = dn * dn * g_h[n * 32 + lane];
        float a1 = 0.f, a2 = 0.f, a3 = 0.f;
        int i = g_off[n], e0 = i + g_cnt[n];
        for (; i + 4 <= e0; i += 4) {
            int2 c0 = g_csr[i], c1 = g_csr[i + 1], c2 = g_csr[i + 2], c3 = g_csr[i + 3];
            a0 += __int_as_float(c0.y) * g_h[c0.x * 32 + lane];
            a1 += __int_as_float(c1.y) * g_h[c1.x * 32 + lane];
            a2 += __int_as_float(c2.y) * g_h[c2.x * 32 + lane];
            a3 += __int_as_float(c3.y) * g_h[c3.x * 32 + lane];
        }
        for (; i < e0; i++) {
            int2 c = g_csr[i];
            a0 += __int_as_float(c.y) * g_h[c.x * 32 + lane];
        }
        out[n * 32 + lane] = tanhf(a0 + a1 + a2 + a3 + bl);
    }
}

// [N,32]@[32,1] -> g_h[n]  (layer 3 pre-multiply)
__global__ void k_mm1(const float* __restrict__ x, const float* __restrict__ W3) {
    int lane = threadIdx.x & 31;
    int warp = (blockIdx.x * blockDim.x + threadIdx.x) >> 5;
    int nwarps = (gridDim.x * blockDim.x) >> 5;
    float w3 = W3[lane];
    for (int n = warp; n < NN; n += nwarps) {
        float v = x[n * 32 + lane] * w3;
#pragma unroll
        for (int o = 16; o > 0; o >>= 1) v += __shfl_down_sync(0xffffffffu, v, o);
        if (lane == 0) g_h[n] = v;
    }
}

// aggregate scalar (layer 3): lanes split the neighbor list
__global__ void k_agg1(const float* __restrict__ b3) {
    int lane = threadIdx.x & 31;
    int warp = (blockIdx.x * blockDim.x + threadIdx.x) >> 5;
    int nwarps = (gridDim.x * blockDim.x) >> 5;
    float b = b3[0];
    for (int n = warp; n < NN; n += nwarps) {
        int s0 = g_off[n], e0 = s0 + g_cnt[n];
        float acc = 0.f;
        for (int i = s0 + lane; i < e0; i += 32) {
            int2 c = g_csr[i];
            acc += __int_as_float(c.y) * g_h[c.x];
        }
#pragma unroll
        for (int o = 16; o > 0; o >>= 1) acc += __shfl_down_sync(0xffffffffu, acc, o);
        if (lane == 0) {
            float dn = g_dis[n];
            g_h4[n] = tanhf(acc + dn * dn * g_h[n] + b);
        }
    }
}

// ---------------- tail1: sort-pool + conv1 + maxpool + conv2 -> g_flat ----------------
__global__ void k_tail1(const float* __restrict__ c1W, const float* __restrict__ c1b,
                        const float* __restrict__ c2W, const float* __restrict__ c2b) {
    __shared__ float s_vals[128];
    __shared__ int   s_idx[128];
    __shared__ float s_xs[KK * DD];
    __shared__ float s_w[2560];
    __shared__ float s_t1[16 * KK];
    __shared__ float s_pool[16 * 30];

    int b = blockIdx.x;
    int t = threadIdx.x;
    int g0 = b * NPG;

    // sort keys desc (index asc tiebreak = jnp.argsort stability)
    float v = (t < NPG) ? g_h4[g0 + t] : -FLT_MAX;
    int   id = (t < NPG) ? t : 0x7fffffff;
    s_vals[t] = v; s_idx[t] = id;
    __syncthreads();
    for (int k = 2; k <= 128; k <<= 1) {
        for (int j = k >> 1; j > 0; j >>= 1) {
            int ixj = t ^ j;
            if (ixj > t) {
                float va = s_vals[t],  vb = s_vals[ixj];
                int   ia = s_idx[t],   ib = s_idx[ixj];
                bool before = (va > vb) || (va == vb && ia < ib);
                bool up = ((t & k) == 0);
                if (up ? !before : before) {
                    s_vals[t] = vb; s_vals[ixj] = va;
                    s_idx[t]  = ib; s_idx[ixj]  = ia;
                }
            }
            __syncthreads();
        }
    }

    // gather top-K features [K][D]
    for (int q = t; q < KK * DD; q += 128) {
        int kk = q / DD, dd = q - kk * DD;
        int node = g0 + s_idx[kk];
        float val;
        if      (dd < 32) val = g_h1[node * 32 + dd];
        else if (dd < 64) val = g_h2[node * 32 + dd - 32];
        else if (dd < 96) val = g_h3[node * 32 + dd - 64];
        else              val = g_h4[node];
        s_xs[q] = val;
    }
    for (int q = t; q < 16 * DD; q += 128) s_w[q] = c1W[q];
    __syncthreads();

    // conv1 (per-slot projection) + relu
    for (int q = t; q < 16 * KK; q += 128) {
        int o = q / KK, kk = q - o * KK;
        float acc = c1b[o];
        for (int dd = 0; dd < DD; dd++) acc += s_xs[kk * DD + dd] * s_w[o * DD + dd];
        s_t1[o * KK + kk] = fmaxf(acc, 0.f);
    }
    __syncthreads();

    // maxpool(2,2) + stage c2W
    for (int q = t; q < 16 * 30; q += 128) {
        int o = q / 30, p = q - o * 30;
        s_pool[o * 30 + p] = fmaxf(s_t1[o * KK + 2 * p], s_t1[o * KK + 2 * p + 1]);
    }
    for (int q = t; q < 2560; q += 128) s_w[q] = c2W[q];
    __syncthreads();

    // conv2 + relu -> g_flat
    for (int q = t; q < 832; q += 128) {
        int o = q / 26, p = q - o * 26;
        float acc = c2b[o];
        for (int i = 0; i < 16; i++) {
#pragma unroll
            for (int tt = 0; tt < 5; tt++)
                acc += s_pool[i * 30 + p + tt] * s_w[o * 80 + i * 5 + tt];
        }
        g_flat[b * 832 + o * 26 + p] = fmaxf(acc, 0.f);
    }
}

// ---------------- tail2: [B,832]@[832,128] -> relu -> @[128,1] ----------------
__global__ void k_tail2(const float* __restrict__ l1W, const float* __restrict__ l1b,
                        const float* __restrict__ l2W, const float* __restrict__ l2b,
                        float* __restrict__ out) {
    __shared__ float s_flat[TG * 832];
    __shared__ float s_red[TG][4];
    int t = threadIdx.x;
    int b0 = blockIdx.x * TG;
    int ng = min(TG, BB - b0);

    for (int q = t; q < ng * 832; q += 128) s_flat[q] = g_flat[b0 * 832 + q];
    __syncthreads();

    float acc[TG];
#pragma unroll
    for (int g = 0; g < TG; g++) acc[g] = 0.f;

    for (int f = 0; f < 832; f++) {
        float wv = l1W[f * 128 + t];
#pragma unroll
        for (int g = 0; g < TG; g++) acc[g] += s_flat[g * 832 + f] * wv;
    }

    float b1v = l1b[t], w2 = l2W[t];
#pragma unroll
    for (int g = 0; g < TG; g++) {
        float p = fmaxf(acc[g] + b1v, 0.f) * w2;
#pragma unroll
        for (int o = 16; o > 0; o >>= 1) p += __shfl_down_sync(0xffffffffu, p, o);
        if ((t & 31) == 0) s_red[g][t >> 5] = p;
    }
    __syncthreads();
    if (t < ng) out[b0 + t] = s_red[t][0] + s_red[t][1] + s_red[t][2] + s_red[t][3] + l2b[0];
}

// ---------------- launch ----------------
extern "C" void kernel_launch(void* const* d_in, const int* in_sizes, int n_in,
                              void* d_out, int out_size) {
    const int*   z1    = (const int*)  d_in[0];
    const int*   z2    = (const int*)  d_in[1];
    const int*   w     = (const int*)  d_in[2];
    const int*   ei    = (const int*)  d_in[3];
    const float* ew    = (const float*)d_in[5];
    const float* emb_w = (const float*)d_in[6];
    const float* emb_z1= (const float*)d_in[7];
    const float* emb_z2= (const float*)d_in[8];
    const float* W0 = (const float*)d_in[9];
    const float* b0 = (const float*)d_in[10];
    const float* W1 = (const float*)d_in[11];
    const float* b1 = (const float*)d_in[12];
    const float* W2 = (const float*)d_in[13];
    const float* b2 = (const float*)d_in[14];
    const float* W3 = (const float*)d_in[15];
    const float* b3 = (const float*)d_in[16];
    const float* c1W = (const float*)d_in[17];
    const float* c1b = (const float*)d_in[18];
    const float* c2W = (const float*)d_in[19];
    const float* c2b = (const float*)d_in[20];
    const float* l1W = (const float*)d_in[21];
    const float* l1b = (const float*)d_in[22];
    const float* l2W = (const float*)d_in[23];
    const float* l2b = (const float*)d_in[24];
    float* out = (float*)d_out;

    const int nb_n = (NN + 255) / 256;
    const int nb_e = (EE + 255) / 256;
    const int nb_scan = (NN + 1023) / 1024;   // 196
    const int GRID = 1480;

    float *h1, *h2, *h3;
    cudaGetSymbolAddress((void**)&h1, g_h1);
    cudaGetSymbolAddress((void**)&h2, g_h2);
    cudaGetSymbolAddress((void**)&h3, g_h3);

    // CSR build
    k_init<<<nb_n, 256>>>();
    k_hist<<<nb_e, 256>>>(ei, ew);
    k_scan1<<<nb_scan, 1024>>>();
    k_scan2<<<1, 256>>>(nb_scan);
    k_scan3<<<nb_scan, 1024>>>();
    k_fill<<<nb_e, 256>>>(ei, ew);

    // GCN stack
    k_mm0  <<<GRID, 256>>>(w, z1, z2, emb_w, emb_z1, emb_z2, W0);
    k_agg32<<<GRID, 256>>>(b0, h1);
    k_mm32 <<<GRID, 256>>>(h1, W1);
    k_agg32<<<GRID, 256>>>(b1, h2);
    k_mm32 <<<GRID, 256>>>(h2, W2);
    k_agg32<<<GRID, 256>>>(b2, h3);
    k_mm1  <<<GRID, 256>>>(h3, W3);
    k_agg1 <<<GRID, 256>>>(b3);

    // tail
    k_tail1<<<BB, 128>>>(c1W, c1b, c2W, c2b);
    k_tail2<<<(BB + TG - 1) / TG, 128>>>(l1W, l1b, l2W, l2b, out);
}

// round 5
// speedup vs baseline: 1.1723x; 1.1600x over previous
#include <cuda_runtime.h>
#include <cuda_bf16.h>
#include <cfloat>
#include <math.h>

#define NN 200000
#define EE 3200000
#define BB 2000
#define NPG 100
#define HH 32
#define KK 60
#define DD 97
#define GRID 1480

// ---------------- device scratch ----------------
__device__ float g_deg[NN];
__device__ float g_dis[NN];
__device__ int   g_cnt[NN];
__device__ int   g_off[NN];
__device__ int   g_cur[NN];
__device__ int2  g_csr[EE];       // .x = src, .y = norm (float bits)
__device__ float g_h [NN * 32];   // x@W scratch
__device__ float g_h1[NN * 32];
__device__ float g_h2[NN * 32];
__device__ float g_h3[NN * 32];
__device__ float g_s [NN];        // h3@W3 scalar
__device__ float g_h4[NN];
__device__ int   g_bsum[256];

// ---------------- CSR build ----------------
__global__ void k_init() {
    int i = blockIdx.x * blockDim.x + threadIdx.x;
    if (i < NN) { g_deg[i] = 1.0f; g_cnt[i] = 0; }  // self loop weight 1
}

__global__ void k_hist(const int* __restrict__ ei, const float* __restrict__ ew) {
    int e = blockIdx.x * blockDim.x + threadIdx.x;
    if (e < EE) {
        int dst = ei[EE + e];
        atomicAdd(&g_deg[dst], ew[e]);
        atomicAdd(&g_cnt[dst], 1);
    }
}

// exclusive scan over cnt (also computes dis = rsqrt(deg))
__global__ void k_scan1() {
    __shared__ int sh[1024];
    int tid = threadIdx.x;
    int i = blockIdx.x * 1024 + tid;
    int v = 0;
    if (i < NN) {
        v = g_cnt[i];
        g_dis[i] = rsqrtf(g_deg[i]);
    }
    sh[tid] = v;
    __syncthreads();
    for (int ofs = 1; ofs < 1024; ofs <<= 1) {
        int t = (tid >= ofs) ? sh[tid - ofs] : 0;
        __syncthreads();
        sh[tid] += t;
        __syncthreads();
    }
    int incl = sh[tid];
    if (i < NN) g_off[i] = incl - v;
    if (tid == 1023) g_bsum[blockIdx.x] = incl;
}

__global__ void k_scan2(int nb) {
    __shared__ int sh[256];
    int tid = threadIdx.x;
    int v = (tid < nb) ? g_bsum[tid] : 0;
    sh[tid] = v;
    __syncthreads();
    for (int ofs = 1; ofs < 256; ofs <<= 1) {
        int t = (tid >= ofs) ? sh[tid - ofs] : 0;
        __syncthreads();
        sh[tid] += t;
        __syncthreads();
    }
    if (tid < nb) g_bsum[tid] = sh[tid] - v;
}

__global__ void k_scan3() {
    int tid = threadIdx.x;
    int i = blockIdx.x * 1024 + tid;
    if (i < NN) {
        int o = g_off[i] + g_bsum[blockIdx.x];
        g_off[i] = o;
        g_cur[i] = o;
    }
}

__global__ void k_fill(const int* __restrict__ ei, const float* __restrict__ ew) {
    int e = blockIdx.x * blockDim.x + threadIdx.x;
    if (e < EE) {
        int src = ei[e];
        int dst = ei[EE + e];
        int pos = atomicAdd(&g_cur[dst], 1);
        float nrm = g_dis[src] * ew[e] * g_dis[dst];
        g_csr[pos] = make_int2(src, __float_as_int(nrm));
    }
}

// ---------------- GCN layers (exact R3 math order) ----------------
// layer 0 matmul: fused embedding gather + [N,96]@[96,32] -> g_h
__global__ void k_mm0(const int* __restrict__ w, const int* __restrict__ z1,
                      const int* __restrict__ z2,
                      const float* __restrict__ emb_w, const float* __restrict__ emb_z1,
                      const float* __restrict__ emb_z2, const float* __restrict__ W0) {
    __shared__ float Ws[96 * 32];
    for (int i = threadIdx.x; i < 96 * 32; i += blockDim.x) Ws[i] = W0[i];
    __syncthreads();
    int lane = threadIdx.x & 31;
    int warp = (blockIdx.x * blockDim.x + threadIdx.x) >> 5;
    int nwarps = (gridDim.x * blockDim.x) >> 5;
    for (int n = warp; n < NN; n += nwarps) {
        float r0 = emb_w [w [n] * 32 + lane];
        float r1 = emb_z1[z1[n] * 32 + lane];
        float r2 = emb_z2[z2[n] * 32 + lane];
        float acc = 0.f;
#pragma unroll
        for (int k = 0; k < 32; k++) acc += __shfl_sync(0xffffffffu, r0, k) * Ws[k * 32 + lane];
#pragma unroll
        for (int k = 0; k < 32; k++) acc += __shfl_sync(0xffffffffu, r1, k) * Ws[(32 + k) * 32 + lane];
#pragma unroll
        for (int k = 0; k < 32; k++) acc += __shfl_sync(0xffffffffu, r2, k) * Ws[(64 + k) * 32 + lane];
        g_h[n * 32 + lane] = acc;
    }
}

// [N,32]@[32,32] -> g_h
__global__ void k_mm32(const float* __restrict__ x, const float* __restrict__ W) {
    __shared__ float Ws[32 * 32];
    for (int i = threadIdx.x; i < 32 * 32; i += blockDim.x) Ws[i] = W[i];
    __syncthreads();
    int lane = threadIdx.x & 31;
    int warp = (blockIdx.x * blockDim.x + threadIdx.x) >> 5;
    int nwarps = (gridDim.x * blockDim.x) >> 5;
    for (int n = warp; n < NN; n += nwarps) {
        float r = x[n * 32 + lane];
        float acc = 0.f;
#pragma unroll
        for (int k = 0; k < 32; k++) acc += __shfl_sync(0xffffffffu, r, k) * Ws[k * 32 + lane];
        g_h[n * 32 + lane] = acc;
    }
}

// aggregate 32ch from g_h over CSR + bias + tanh; 4 independent chains
__global__ void k_agg32(const float* __restrict__ bias, float* __restrict__ out) {
    int lane = threadIdx.x & 31;
    int warp = (blockIdx.x * blockDim.x + threadIdx.x) >> 5;
    int nwarps = (gridDim.x * blockDim.x) >> 5;
    float bl = bias[lane];
    for (int n = warp; n < NN; n += nwarps) {
        float dn = g_dis[n];
        float a0 = dn * dn * g_h[n * 32 + lane];
        float a1 = 0.f, a2 = 0.f, a3 = 0.f;
        int i = g_off[n], e0 = i + g_cnt[n];
        for (; i + 4 <= e0; i += 4) {
            int2 c0 = g_csr[i], c1 = g_csr[i + 1], c2 = g_csr[i + 2], c3 = g_csr[i + 3];
            a0 += __int_as_float(c0.y) * g_h[c0.x * 32 + lane];
            a1 += __int_as_float(c1.y) * g_h[c1.x * 32 + lane];
            a2 += __int_as_float(c2.y) * g_h[c2.x * 32 + lane];
            a3 += __int_as_float(c3.y) * g_h[c3.x * 32 + lane];
        }
        for (; i < e0; i++) {
            int2 c = g_csr[i];
            a0 += __int_as_float(c.y) * g_h[c.x * 32 + lane];
        }
        out[n * 32 + lane] = tanhf(a0 + a1 + a2 + a3 + bl);
    }
}

// 3rd aggregate with fused h3@W3 scalar epilogue (same op order as old mm1)
__global__ void k_agg32f(const float* __restrict__ bias, const float* __restrict__ W3,
                         float* __restrict__ out) {
    int lane = threadIdx.x & 31;
    int warp = (blockIdx.x * blockDim.x + threadIdx.x) >> 5;
    int nwarps = (gridDim.x * blockDim.x) >> 5;
    float bl = bias[lane];
    float w3 = W3[lane];
    for (int n = warp; n < NN; n += nwarps) {
        float dn = g_dis[n];
        float a0 = dn * dn * g_h[n * 32 + lane];
        float a1 = 0.f, a2 = 0.f, a3 = 0.f;
        int i = g_off[n], e0 = i + g_cnt[n];
        for (; i + 4 <= e0; i += 4) {
            int2 c0 = g_csr[i], c1 = g_csr[i + 1], c2 = g_csr[i + 2], c3 = g_csr[i + 3];
            a0 += __int_as_float(c0.y) * g_h[c0.x * 32 + lane];
            a1 += __int_as_float(c1.y) * g_h[c1.x * 32 + lane];
            a2 += __int_as_float(c2.y) * g_h[c2.x * 32 + lane];
            a3 += __int_as_float(c3.y) * g_h[c3.x * 32 + lane];
        }
        for (; i < e0; i++) {
            int2 c = g_csr[i];
            a0 += __int_as_float(c.y) * g_h[c.x * 32 + lane];
        }
        float y = tanhf(a0 + a1 + a2 + a3 + bl);
        out[n * 32 + lane] = y;
        float v = y * w3;
#pragma unroll
        for (int o = 16; o > 0; o >>= 1) v += __shfl_down_sync(0xffffffffu, v, o);
        if (lane == 0) g_s[n] = v;
    }
}

// aggregate scalar (layer 3): lanes split the neighbor list
__global__ void k_agg1(const float* __restrict__ b3) {
    int lane = threadIdx.x & 31;
    int warp = (blockIdx.x * blockDim.x + threadIdx.x) >> 5;
    int nwarps = (gridDim.x * blockDim.x) >> 5;
    float b = b3[0];
    for (int n = warp; n < NN; n += nwarps) {
        int s0 = g_off[n], e0 = s0 + g_cnt[n];
        float acc = 0.f;
        for (int i = s0 + lane; i < e0; i += 32) {
            int2 c = g_csr[i];
            acc += __int_as_float(c.y) * g_s[c.x];
        }
#pragma unroll
        for (int o = 16; o > 0; o >>= 1) acc += __shfl_down_sync(0xffffffffu, acc, o);
        if (lane == 0) {
            float dn = g_dis[n];
            g_h4[n] = tanhf(acc + dn * dn * g_s[n] + b);
        }
    }
}

// ---------------- fused tail: 2 graphs per block ----------------
__global__ void k_tail(const float* __restrict__ c1W, const float* __restrict__ c1b,
                       const float* __restrict__ c2W, const float* __restrict__ c2b,
                       const float* __restrict__ l1W, const float* __restrict__ l1b,
                       const float* __restrict__ l2W, const float* __restrict__ l2b,
                       float* __restrict__ out) {
    __shared__ float s_vals[128];
    __shared__ int   s_idx[128];
    __shared__ float s_xs[KK * DD];       // 23280B
    __shared__ float s_w1[16 * DD];       // c1W 6208B
    __shared__ float s_w2[2560];          // c2W 10240B
    __shared__ float s_t1[16 * KK];
    __shared__ float s_pool[16 * 30];
    __shared__ float s_flat[2][832];
    __shared__ float s_red[2][4];

    int t = threadIdx.x;
    int b0 = blockIdx.x * 2;

    // stage conv weights once
    for (int q = t; q < 16 * DD; q += 128) s_w1[q] = c1W[q];
    for (int q = t; q < 2560; q += 128) s_w2[q] = c2W[q];

    for (int g = 0; g < 2; g++) {
        int b = b0 + g;
        int g0 = b * NPG;

        // sort keys desc (index asc tiebreak = jnp.argsort stability)
        float v = (t < NPG) ? g_h4[g0 + t] : -FLT_MAX;
        int   id = (t < NPG) ? t : 0x7fffffff;
        __syncthreads();               // protect s_vals reuse across g
        s_vals[t] = v; s_idx[t] = id;
        __syncthreads();
        for (int k = 2; k <= 128; k <<= 1) {
            for (int j = k >> 1; j > 0; j >>= 1) {
                int ixj = t ^ j;
                if (ixj > t) {
                    float va = s_vals[t],  vb = s_vals[ixj];
                    int   ia = s_idx[t],   ib = s_idx[ixj];
                    bool before = (va > vb) || (va == vb && ia < ib);
                    bool up = ((t & k) == 0);
                    if (up ? !before : before) {
                        s_vals[t] = vb; s_vals[ixj] = va;
                        s_idx[t]  = ib; s_idx[ixj]  = ia;
                    }
                }
                __syncthreads();
            }
        }

        // gather top-K features [K][D]
        for (int q = t; q < KK * DD; q += 128) {
            int kk = q / DD, dd = q - kk * DD;
            int node = g0 + s_idx[kk];
            float val;
            if      (dd < 32) val = g_h1[node * 32 + dd];
            else if (dd < 64) val = g_h2[node * 32 + dd - 32];
            else if (dd < 96) val = g_h3[node * 32 + dd - 64];
            else              val = g_h4[node];
            s_xs[q] = val;
        }
        __syncthreads();

        // conv1 (per-slot projection) + relu
        for (int q = t; q < 16 * KK; q += 128) {
            int o = q / KK, kk = q - o * KK;
            float acc = c1b[o];
            for (int dd = 0; dd < DD; dd++) acc += s_xs[kk * DD + dd] * s_w1[o * DD + dd];
            s_t1[o * KK + kk] = fmaxf(acc, 0.f);
        }
        __syncthreads();

        // maxpool(2,2)
        for (int q = t; q < 16 * 30; q += 128) {
            int o = q / 30, p = q - o * 30;
            s_pool[o * 30 + p] = fmaxf(s_t1[o * KK + 2 * p], s_t1[o * KK + 2 * p + 1]);
        }
        __syncthreads();

        // conv2 + relu -> s_flat[g]
        for (int q = t; q < 832; q += 128) {
            int o = q / 26, p = q - o * 26;
            float acc = c2b[o];
            for (int i = 0; i < 16; i++) {
#pragma unroll
                for (int tt = 0; tt < 5; tt++)
                    acc += s_pool[i * 30 + p + tt] * s_w2[o * 80 + i * 5 + tt];
            }
            s_flat[g][o * 26 + p] = fmaxf(acc, 0.f);
        }
        __syncthreads();
    }

    // l1 for both graphs: single pass over l1W
    float acc0 = l1b[t], acc1 = acc0;
    for (int f = 0; f < 832; f++) {
        float wv = l1W[f * 128 + t];
        acc0 += s_flat[0][f] * wv;
        acc1 += s_flat[1][f] * wv;
    }
    float w2 = l2W[t];
    float y0 = fmaxf(acc0, 0.f) * w2;
    float y1 = fmaxf(acc1, 0.f) * w2;
#pragma unroll
    for (int o = 16; o > 0; o >>= 1) {
        y0 += __shfl_down_sync(0xffffffffu, y0, o);
        y1 += __shfl_down_sync(0xffffffffu, y1, o);
    }
    if ((t & 31) == 0) { s_red[0][t >> 5] = y0; s_red[1][t >> 5] = y1; }
    __syncthreads();
    if (t < 2)
        out[b0 + t] = s_red[t][0] + s_red[t][1] + s_red[t][2] + s_red[t][3] + l2b[0];
}

// ---------------- launch ----------------
extern "C" void kernel_launch(void* const* d_in, const int* in_sizes, int n_in,
                              void* d_out, int out_size) {
    const int*   z1    = (const int*)  d_in[0];
    const int*   z2    = (const int*)  d_in[1];
    const int*   w     = (const int*)  d_in[2];
    const int*   ei    = (const int*)  d_in[3];
    const float* ew    = (const float*)d_in[5];
    const float* emb_w = (const float*)d_in[6];
    const float* emb_z1= (const float*)d_in[7];
    const float* emb_z2= (const float*)d_in[8];
    const float* W0 = (const float*)d_in[9];
    const float* b0 = (const float*)d_in[10];
    const float* W1 = (const float*)d_in[11];
    const float* b1 = (const float*)d_in[12];
    const float* W2 = (const float*)d_in[13];
    const float* b2 = (const float*)d_in[14];
    const float* W3 = (const float*)d_in[15];
    const float* b3 = (const float*)d_in[16];
    const float* c1W = (const float*)d_in[17];
    const float* c1b = (const float*)d_in[18];
    const float* c2W = (const float*)d_in[19];
    const float* c2b = (const float*)d_in[20];
    const float* l1W = (const float*)d_in[21];
    const float* l1b = (const float*)d_in[22];
    const float* l2W = (const float*)d_in[23];
    const float* l2b = (const float*)d_in[24];
    float* out = (float*)d_out;

    const int nb_n = (NN + 255) / 256;
    const int nb_e = (EE + 255) / 256;
    const int nb_scan = (NN + 1023) / 1024;   // 196

    float *h1, *h2, *h3;
    cudaGetSymbolAddress((void**)&h1, g_h1);
    cudaGetSymbolAddress((void**)&h2, g_h2);
    cudaGetSymbolAddress((void**)&h3, g_h3);

    // CSR build
    k_init<<<nb_n, 256>>>();
    k_hist<<<nb_e, 256>>>(ei, ew);
    k_scan1<<<nb_scan, 1024>>>();
    k_scan2<<<1, 256>>>(nb_scan);
    k_scan3<<<nb_scan, 1024>>>();
    k_fill<<<nb_e, 256>>>(ei, ew);

    // GCN stack (R3-proven math order; mm1 fused into 3rd agg)
    k_mm0   <<<GRID, 256>>>(w, z1, z2, emb_w, emb_z1, emb_z2, W0);
    k_agg32 <<<GRID, 256>>>(b0, h1);
    k_mm32  <<<GRID, 256>>>(h1, W1);
    k_agg32 <<<GRID, 256>>>(b1, h2);
    k_mm32  <<<GRID, 256>>>(h2, W2);
    k_agg32f<<<GRID, 256>>>(b2, W3, h3);
    k_agg1  <<<GRID, 256>>>(b3);

    // fused tail, 2 graphs per block
    k_tail<<<BB / 2, 128>>>(c1W, c1b, c2W, c2b, l1W, l1b, l2W, l2b, out);
}